// round 3
// baseline (speedup 1.0000x reference)
#include <cuda_runtime.h>
#include <cstdint>

// embedding_bag(mode='mean'): B bags over a [V,64] fp32 table.
// One HALF-WARP per bag; sublane s (0..15) owns one float4 (cols 4s..4s+3).
// 16 lanes x 16B = one 256B row per half-warp => each LDG.E.128 warp
// instruction fetches TWO full rows (512B). Unroll x8 => 4KB outstanding
// per warp in the steady state.
__global__ __launch_bounds__(128)
void embag_mean_kernel(const void* __restrict__ indices_raw,
                       const void* __restrict__ offsets_raw,
                       const float* __restrict__ weight,
                       float* __restrict__ out,
                       int num_bags, long long total_indices) {
    const int warp_global = (int)((blockIdx.x * (unsigned)blockDim.x + threadIdx.x) >> 5);
    const int lane = threadIdx.x & 31;
    const int half = lane >> 4;        // which bag within the warp
    const int sub  = lane & 15;        // float4 column group within the row
    const int bag  = 2 * warp_global + half;
    if (bag >= num_bags) return;

    // Inline dtype detection (int64 vs int32 indices). Values < 2^31, so for
    // an int64 (LE) buffer every odd 32-bit word is zero; for int32 the odd
    // words are random ids (P[all 4 zero] ~ 1e-24). Uniform -> no divergence;
    // broadcast addresses -> cached.
    const int* wprobe = (const int*)indices_raw;
    int allz = 1;
    #pragma unroll
    for (int k = 1; k < 9; k += 2) allz &= (__ldg(&wprobe[k]) == 0);
    const bool is64 = (allz != 0);

    const long long* __restrict__ idx64 = (const long long*)indices_raw;
    const int*       __restrict__ idx32 = (const int*)indices_raw;
    const long long* __restrict__ off64 = (const long long*)offsets_raw;
    const int*       __restrict__ off32 = (const int*)offsets_raw;

    long long start, end;
    if (is64) {
        start = __ldg(&off64[bag]);
        end   = (bag + 1 < num_bags) ? __ldg(&off64[bag + 1]) : total_indices;
    } else {
        start = (long long)__ldg(&off32[bag]);
        end   = (bag + 1 < num_bags) ? (long long)__ldg(&off32[bag + 1]) : total_indices;
    }

    float4 acc0 = make_float4(0.f, 0.f, 0.f, 0.f);
    float4 acc1 = make_float4(0.f, 0.f, 0.f, 0.f);

    long long i = start;
    // Main loop: 8 independent row gathers in flight per lane.
    for (; i + 8 <= end; i += 8) {
        unsigned r[8];
        if (is64) {
            #pragma unroll
            for (int k = 0; k < 8; ++k) r[k] = (unsigned)__ldg(&idx64[i + k]);
        } else {
            #pragma unroll
            for (int k = 0; k < 8; ++k) r[k] = (unsigned)__ldg(&idx32[i + k]);
        }
        float4 v[8];
        #pragma unroll
        for (int k = 0; k < 8; ++k)
            v[k] = __ldg((const float4*)(weight + (size_t)r[k] * 64) + sub);

        acc0.x += (v[0].x + v[1].x) + (v[2].x + v[3].x);
        acc0.y += (v[0].y + v[1].y) + (v[2].y + v[3].y);
        acc0.z += (v[0].z + v[1].z) + (v[2].z + v[3].z);
        acc0.w += (v[0].w + v[1].w) + (v[2].w + v[3].w);
        acc1.x += (v[4].x + v[5].x) + (v[6].x + v[7].x);
        acc1.y += (v[4].y + v[5].y) + (v[6].y + v[7].y);
        acc1.z += (v[4].z + v[5].z) + (v[6].z + v[7].z);
        acc1.w += (v[4].w + v[5].w) + (v[6].w + v[7].w);
    }
    // 4-wide tail
    for (; i + 4 <= end; i += 4) {
        unsigned r[4];
        if (is64) {
            #pragma unroll
            for (int k = 0; k < 4; ++k) r[k] = (unsigned)__ldg(&idx64[i + k]);
        } else {
            #pragma unroll
            for (int k = 0; k < 4; ++k) r[k] = (unsigned)__ldg(&idx32[i + k]);
        }
        float4 v[4];
        #pragma unroll
        for (int k = 0; k < 4; ++k)
            v[k] = __ldg((const float4*)(weight + (size_t)r[k] * 64) + sub);
        acc0.x += (v[0].x + v[1].x) + (v[2].x + v[3].x);
        acc0.y += (v[0].y + v[1].y) + (v[2].y + v[3].y);
        acc0.z += (v[0].z + v[1].z) + (v[2].z + v[3].z);
        acc0.w += (v[0].w + v[1].w) + (v[2].w + v[3].w);
    }
    // Scalar tail
    for (; i < end; ++i) {
        unsigned r = is64 ? (unsigned)__ldg(&idx64[i]) : (unsigned)__ldg(&idx32[i]);
        float4 v = __ldg((const float4*)(weight + (size_t)r * 64) + sub);
        acc0.x += v.x; acc0.y += v.y; acc0.z += v.z; acc0.w += v.w;
    }

    float4 acc;
    acc.x = acc0.x + acc1.x;
    acc.y = acc0.y + acc1.y;
    acc.z = acc0.z + acc1.z;
    acc.w = acc0.w + acc1.w;

    const long long cnt = end - start;
    const float inv = 1.0f / (float)(cnt > 0 ? cnt : 1);
    acc.x *= inv; acc.y *= inv; acc.z *= inv; acc.w *= inv;

    ((float4*)out)[(size_t)bag * 16 + sub] = acc;
}

extern "C" void kernel_launch(void* const* d_in, const int* in_sizes, int n_in,
                              void* d_out, int out_size) {
    // metadata order: indices [T], offsets [B], weight [V*D]
    const void*  indices = d_in[0];
    const void*  offsets = d_in[1];
    const float* weight  = (const float*)d_in[2];
    float*       out     = (float*)d_out;

    const int       num_bags      = in_sizes[1];
    const long long total_indices = in_sizes[0];

    // 2 bags per warp, 4 warps per block -> 8 bags per block.
    const int bags_per_block = 8;
    const int blocks = (num_bags + bags_per_block - 1) / bags_per_block;
    embag_mean_kernel<<<blocks, 128>>>(indices, offsets, weight, out,
                                       num_bags, total_indices);
}